// round 16
// baseline (speedup 1.0000x reference)
#include <cuda_runtime.h>
#include <cuda_fp16.h>
#include <cstdint>

// ============================================================================
// R16 = R15 (passing, 149.5us) with ONE change: occupancy 8 -> 12 warps/SM.
//   warp tile 64x64 -> 32x64 (acc 64 regs), CTA tile 64x128, 3 CTAs/SM via
//   launch_bounds(128,3); smem to 2 stages (R2's proven two-sync schedule).
// Per-element K-order identical -> bit-identical output.
//   pre:  x, Wq, Wo -> half (rne)
//   K1: meas = cumprod8(cos(x_h @ Wq_h^T)) -> g_meash (half)
//   K2: out  = meas_h @ Wo_h^T             -> d_out (fp32)
// k/v are dead compute in the reference; skipped.
// ============================================================================

#define BM 64
#define BN 128
#define BK 64                        // halves of K per chunk (4 k16 steps)
#define KTOT 512
#define MTOT 32768
#define NCHUNK (KTOT / BK)           // 8
#define NTHREADS 128

#define AH 72                        // halves per smem row (64 + 8 pad) = 144B
#define A_TILE_H (BM * AH)           // 4608 halves
#define B_TILE_H (BN * AH)           // 9216 halves
#define STAGE_H (A_TILE_H + B_TILE_H)       // 13824 halves
#define NSTAGE 2
#define SMEM_BYTES (NSTAGE * STAGE_H * 2)   // 55296 B

// Device scratch (static arrays; no runtime allocation)
__device__ __half g_xh[(size_t)MTOT * KTOT];     // 32 MB
__device__ __half g_meash[(size_t)MTOT * KTOT];  // 32 MB
__device__ __half g_wq[KTOT * KTOT];             // 512 KB
__device__ __half g_wo[KTOT * KTOT];             // 512 KB

// ---------------------------------------------------------------------------
static __device__ __forceinline__ uint32_t smem_u32(const void* p) {
    uint32_t a;
    asm("{ .reg .u64 t; cvta.to.shared.u64 t, %1; cvt.u32.u64 %0, t; }"
        : "=r"(a) : "l"(p));
    return a;
}

static __device__ __forceinline__ void cp_async16(uint32_t dst, const void* src) {
    asm volatile("cp.async.cg.shared.global [%0], [%1], 16;"
                 :: "r"(dst), "l"(src) : "memory");
}
static __device__ __forceinline__ void cp_commit() {
    asm volatile("cp.async.commit_group;" ::: "memory");
}
static __device__ __forceinline__ void cp_wait1() {
    asm volatile("cp.async.wait_group 1;" ::: "memory");
}
static __device__ __forceinline__ void cp_wait0() {
    asm volatile("cp.async.wait_group 0;" ::: "memory");
}

static __device__ __forceinline__ void ldsm_x4(
    uint32_t addr, uint32_t& r0, uint32_t& r1, uint32_t& r2, uint32_t& r3) {
    asm volatile("ldmatrix.sync.aligned.m8n8.x4.shared.b16 {%0,%1,%2,%3}, [%4];"
                 : "=r"(r0), "=r"(r1), "=r"(r2), "=r"(r3) : "r"(addr));
}

// m16n8k16 fp16 inputs, fp32 accumulate
static __device__ __forceinline__ void mma_f16(
    float* c, uint32_t a0, uint32_t a1, uint32_t a2, uint32_t a3,
    uint32_t b0, uint32_t b1) {
    asm volatile(
        "mma.sync.aligned.m16n8k16.row.col.f32.f16.f16.f32 "
        "{%0,%1,%2,%3}, {%4,%5,%6,%7}, {%8,%9}, {%0,%1,%2,%3};"
        : "+f"(c[0]), "+f"(c[1]), "+f"(c[2]), "+f"(c[3])
        : "r"(a0), "r"(a1), "r"(a2), "r"(a3), "r"(b0), "r"(b1));
}

// Exclusive-prefix cumprod of cos over one 8-wide head held by a lane quad.
// Thread (tig = lane&3) holds cols 2*tig, 2*tig+1 of its row.
static __device__ __forceinline__ float2 head_scan(float v0, float v1, int tig) {
    const float c0 = __cosf(v0);
    const float c1 = __cosf(v1);
    const float p = c0 * c1;
    const float pm1 = __shfl_up_sync(0xffffffffu, p, 1, 4);
    const float pm2 = __shfl_up_sync(0xffffffffu, p, 2, 4);
    const float pm3 = __shfl_up_sync(0xffffffffu, p, 3, 4);
    float ex = 1.0f;
    if (tig >= 1) ex *= pm1;
    if (tig >= 2) ex *= pm2;
    if (tig >= 3) ex *= pm3;
    float2 r;
    r.x = ex * c0;      // cumprod through col 2*tig
    r.y = ex * p;       // cumprod through col 2*tig+1
    return r;
}

// ---------------------------------------------------------------------------
// fp32 -> fp16 (rne): DST 0 = x, 1 = Wq, 2 = Wo
// ---------------------------------------------------------------------------
template <int DST>
__global__ void cvt_half(const float* __restrict__ src) {
    __half* __restrict__ dst = (DST == 0) ? g_xh : (DST == 1) ? g_wq : g_wo;
    const size_t i = ((size_t)blockIdx.x * blockDim.x + threadIdx.x) * 8;
    const float4 v0 = *(const float4*)(src + i);
    const float4 v1 = *(const float4*)(src + i + 4);
    const __half2 h0 = __floats2half2_rn(v0.x, v0.y);
    const __half2 h1 = __floats2half2_rn(v0.z, v0.w);
    const __half2 h2 = __floats2half2_rn(v1.x, v1.y);
    const __half2 h3 = __floats2half2_rn(v1.z, v1.w);
    uint4 o;
    o.x = *(const uint32_t*)&h0;
    o.y = *(const uint32_t*)&h1;
    o.z = *(const uint32_t*)&h2;
    o.w = *(const uint32_t*)&h3;
    *(uint4*)(dst + i) = o;
}

// ---------------------------------------------------------------------------
// D[m_base.., n_base..] = A . W^T over K=512.  4 warps (2x2), warp tile 32x64.
// MEASURE: epilogue = cos+cumprod8 along n -> g_meash.  else -> Outp (fp32).
// ---------------------------------------------------------------------------
template <bool MEASURE>
__global__ void __launch_bounds__(NTHREADS, 3) qgemm(float* __restrict__ Outp) {
    extern __shared__ __half smh[];
    const uint32_t sb = smem_u32(smh);
    const int tid = threadIdx.x;
    const int wid = tid >> 5;
    const int lane = tid & 31;
    const int g = lane >> 2;       // group id (row / n within fragment)
    const int tig = lane & 3;      // k-pair selector
    const int lrow = lane & 7;     // ldmatrix: row within 8x8 matrix
    const int lm = lane >> 3;      // ldmatrix: matrix id 0..3

    // N-tiles vary fastest (blockIdx.x) so wave-adjacent CTAs share A rows in L2
    const int n_base = blockIdx.x * BN;
    const int m_base = blockIdx.y * BM;

    const __half* __restrict__ A = MEASURE ? g_xh : g_meash;
    const __half* __restrict__ W = MEASURE ? g_wq : g_wo;

    // ---- async stage loader: A 64x64h + B 128x64h, 16B granules ----
    auto load_stage = [&](int s, int kb) {
        const uint32_t sa = sb + (uint32_t)(s * STAGE_H) * 2u;
        const uint32_t sw = sa + (uint32_t)A_TILE_H * 2u;
#pragma unroll
        for (int i = 0; i < 4; i++) {      // 64 rows x 8 granules = 512
            const int p = tid + i * NTHREADS;
            const int row = p >> 3;
            const int c = p & 7;
            cp_async16(sa + (uint32_t)(row * AH + c * 8) * 2u,
                       A + (size_t)(m_base + row) * KTOT + kb + c * 8);
        }
#pragma unroll
        for (int i = 0; i < 8; i++) {      // 128 rows x 8 granules = 1024
            const int p = tid + i * NTHREADS;
            const int row = p >> 3;
            const int c = p & 7;
            cp_async16(sw + (uint32_t)(row * AH + c * 8) * 2u,
                       W + (size_t)(n_base + row) * KTOT + kb + c * 8);
        }
        cp_commit();
    };

    load_stage(0, 0);
    load_stage(1, BK);

    const int warp_m = wid & 1;    // 2 x 32 rows
    const int warp_n = wid >> 1;   // 2 x 64 cols

    // ldmatrix per-lane offsets (halves), identity fragment map (proven):
    // A mats 0..3 = (r,k0),(r+8,k0),(r,k8),(r+8,k8)
    const int aoff = ((lm & 1) * 8 + lrow) * AH + (lm >> 1) * 8;
    // B mats 0..3 = (n0-7,k0),(n0-7,k8),(n8-15,k0),(n8-15,k8)
    const int boff = ((lm >> 1) * 8 + lrow) * AH + (lm & 1) * 8;

    float acc[2][8][4];
#pragma unroll
    for (int mt = 0; mt < 2; mt++)
#pragma unroll
        for (int nt = 0; nt < 8; nt++)
#pragma unroll
            for (int i = 0; i < 4; i++) acc[mt][nt][i] = 0.0f;

#pragma unroll 1
    for (int kc = 0; kc < NCHUNK; kc++) {
        // R2-style 2-stage schedule: wait, sync, compute, sync, prefetch.
        if (kc == NCHUNK - 1) cp_wait0(); else cp_wait1();
        __syncthreads();

        const uint32_t baseA = sb + (uint32_t)((kc & 1) * STAGE_H) * 2u;
        const uint32_t baseB = baseA + (uint32_t)A_TILE_H * 2u;

#pragma unroll
        for (int ks = 0; ks < 4; ks++) {       // four k16 steps per chunk
            const int kh = ks * 16;            // half offset of this k16 block
            uint32_t af[2][4];
#pragma unroll
            for (int mt = 0; mt < 2; mt++)
                ldsm_x4(baseA +
                            (uint32_t)((warp_m * 32 + mt * 16) * AH + kh + aoff) * 2u,
                        af[mt][0], af[mt][1], af[mt][2], af[mt][3]);
            uint32_t bf[8][2];
#pragma unroll
            for (int p = 0; p < 4; p++)
                ldsm_x4(baseB +
                            (uint32_t)((warp_n * 64 + p * 16) * AH + kh + boff) * 2u,
                        bf[2 * p][0], bf[2 * p][1], bf[2 * p + 1][0],
                        bf[2 * p + 1][1]);
#pragma unroll
            for (int mt = 0; mt < 2; mt++)
#pragma unroll
                for (int nt = 0; nt < 8; nt++)
                    mma_f16(acc[mt][nt], af[mt][0], af[mt][1], af[mt][2],
                            af[mt][3], bf[nt][0], bf[nt][1]);
        }
        __syncthreads();
        const int nk = kc + 2;
        if (nk < NCHUNK) load_stage(kc & 1, nk * BK);
    }

    // ---- epilogue: c0=(g,2tig) c1=(g,2tig+1) c2=(g+8,2tig) c3=(g+8,2tig+1)
#pragma unroll
    for (int mt = 0; mt < 2; mt++) {
#pragma unroll
        for (int nt = 0; nt < 8; nt++) {
            const int r0 = m_base + warp_m * 32 + mt * 16 + g;
            const int n0 = n_base + warp_n * 64 + nt * 8 + 2 * tig;
            const float* c = acc[mt][nt];
            if (MEASURE) {
                // each m16n8 tile spans exactly one 8-wide head
                const float2 lo = head_scan(c[0], c[1], tig);   // row r0
                const float2 hi = head_scan(c[2], c[3], tig);   // row r0+8
                const __half2 hlo = __floats2half2_rn(lo.x, lo.y);
                const __half2 hhi = __floats2half2_rn(hi.x, hi.y);
                *(__half2*)(g_meash + (size_t)r0 * KTOT + n0) = hlo;
                *(__half2*)(g_meash + (size_t)(r0 + 8) * KTOT + n0) = hhi;
            } else {
                *(float2*)(Outp + (size_t)r0 * KTOT + n0) =
                    make_float2(c[0], c[1]);
                *(float2*)(Outp + (size_t)(r0 + 8) * KTOT + n0) =
                    make_float2(c[2], c[3]);
            }
        }
    }
}

// ---------------------------------------------------------------------------
// Inputs (metadata order): x, Wq, Wk, Wv, Wo.  Wk/Wv are dead compute.
// ---------------------------------------------------------------------------
extern "C" void kernel_launch(void* const* d_in, const int* in_sizes, int n_in,
                              void* d_out, int out_size) {
    const float* x = (const float*)d_in[0];
    const float* Wq = (const float*)d_in[1];
    const float* Wo = (const float*)d_in[4];

    static bool attr_set = false;
    if (!attr_set) {
        cudaFuncSetAttribute(qgemm<true>,
                             cudaFuncAttributeMaxDynamicSharedMemorySize,
                             SMEM_BYTES);
        cudaFuncSetAttribute(qgemm<false>,
                             cudaFuncAttributeMaxDynamicSharedMemorySize,
                             SMEM_BYTES);
        attr_set = true;
    }

    const size_t XN = (size_t)MTOT * KTOT;   // 16777216
    const size_t WN = (size_t)KTOT * KTOT;   // 262144
    cvt_half<0><<<(unsigned)(XN / (256 * 8)), 256>>>(x);
    cvt_half<1><<<(unsigned)(WN / (256 * 8)), 256>>>(Wq);
    cvt_half<2><<<(unsigned)(WN / (256 * 8)), 256>>>(Wo);

    dim3 grid(KTOT / BN, MTOT / BM);  // (4, 512): n fastest for L2 reuse of A
    qgemm<true><<<grid, NTHREADS, SMEM_BYTES>>>(nullptr);
    qgemm<false><<<grid, NTHREADS, SMEM_BYTES>>>((float*)d_out);
}